// round 14
// baseline (speedup 1.0000x reference)
#include <cuda_runtime.h>
#include <cstdint>

#define N_PAT 8192
#define N_BITS 4096
#define NTHR 256          // per CTA: 8 warps; 16 rows per thread
#define COLBYTES (N_PAT * 2)   // 16384 = 1 << 14

// c'[i][r] = -state[i]*W[r][i] in {+1,-1}, stored s16.
// Halved domain: g = h/2; flip i => g_new = g + c'[i].
__device__ short g_C[(size_t)N_BITS * N_PAT];  // 64 MB scratch
__device__ int   g_g0[N_PAT];

// ---------------------------------------------------------------------------
__global__ void k_buildU(const float* __restrict__ W, const float* __restrict__ state) {
    __shared__ unsigned char sm[32][132];
    int i0 = blockIdx.x * 32;
    int r0 = blockIdx.y * 128;
    int tx = threadIdx.x, ty = threadIdx.y;
    float v = state[i0 + tx];
    #pragma unroll
    for (int j = 0; j < 16; j++) {
        float w = W[(size_t)(r0 + ty + j * 8) * N_BITS + i0 + tx];
        sm[tx][ty + j * 8] = (w == v) ? 1 : 0;
    }
    __syncthreads();
    #pragma unroll
    for (int jj = 0; jj < 4; jj++) {
        int il = ty + jj * 8;
        short4 val;
        val.x = (short)(1 - 2 * (int)sm[il][4 * tx + 0]);
        val.y = (short)(1 - 2 * (int)sm[il][4 * tx + 1]);
        val.z = (short)(1 - 2 * (int)sm[il][4 * tx + 2]);
        val.w = (short)(1 - 2 * (int)sm[il][4 * tx + 3]);
        *reinterpret_cast<short4*>(&g_C[(size_t)(i0 + il) * N_PAT + r0 + 4 * tx]) = val;
    }
}

// ---------------------------------------------------------------------------
__global__ void k_h0t(const float* __restrict__ state, float* __restrict__ out) {
    int t = blockIdx.x * blockDim.x + threadIdx.x;   // 0..4095 (row pair)
    out[t] = state[t];
    const int* col = reinterpret_cast<const int*>(g_C) + t;
    int acc2 = 0;
    #pragma unroll 8
    for (int i = 0; i < N_BITS; i++)
        acc2 = __vadd2(acc2, col[(size_t)i * (N_PAT / 2)]);
    int lo = (int)(short)(acc2 & 0xFFFF);
    int hi = acc2 >> 16;
    g_g0[2 * t]     = -(lo >> 1);
    g_g0[2 * t + 1] = -(hi >> 1);
}

// ---------------------------------------------------------------------------
__device__ __forceinline__ uint32_t smem_u32(const void* p) {
    uint32_t a;
    asm("{ .reg .u64 tmp; cvta.to.shared.u64 tmp, %1; cvt.u32.u64 %0, tmp; }" : "=r"(a) : "l"(p));
    return a;
}
#define MBAR_INIT(a, c) \
    asm volatile("mbarrier.init.shared.b64 [%0], %1;" :: "r"(a), "r"(c) : "memory")
#define MBAR_ARRIVE_LOCAL(a) \
    asm volatile("mbarrier.arrive.release.cta.shared::cta.b64 _, [%0];" :: "r"(a) : "memory")
#define MBAR_ARRIVE_PEER(a, rk) \
    asm volatile("{\n\t.reg .b32 ra;\n\t" \
                 "mapa.shared::cluster.u32 ra, %0, %1;\n\t" \
                 "mbarrier.arrive.release.cluster.shared::cluster.b64 _, [ra];\n\t}" \
                 :: "r"(a), "r"(rk) : "memory")
#define ST_PEER_B64(a, rk, v) \
    asm volatile("{\n\t.reg .b32 ra;\n\t" \
                 "mapa.shared::cluster.u32 ra, %0, %1;\n\t" \
                 "st.shared::cluster.b64 [ra], %2;\n\t}" \
                 :: "r"(a), "r"(rk), "l"(v) : "memory")
#define MBAR_WAIT_CL(a, par) do {                                                     \
    asm volatile(                                                                     \
        "{\n\t.reg .pred P;\n\t"                                                      \
        "WL_%=:\n\t"                                                                  \
        "mbarrier.try_wait.parity.acquire.cluster.shared::cta.b64 P, [%0], %1, 0x989680;\n\t" \
        "@P bra.uni WD_%=;\n\t"                                                       \
        "bra.uni WL_%=;\n\t"                                                          \
        "WD_%=:\n\t}"                                                                 \
        :: "r"(a), "r"(par) : "memory");                                              \
} while (0)
#define CLUSTER_SYNC() do {                                                \
    asm volatile("barrier.cluster.arrive.aligned;" ::: "memory");          \
    asm volatile("barrier.cluster.wait.aligned;"   ::: "memory");          \
} while (0)

// ---------------------------------------------------------------------------
// Main: 2-CTA cluster, 256 threads/CTA (8 warps), each CTA owns 4096 rows
// (16 rows/thread as 8 s16x2 regs g + m = relu(g)). TWO bits per sync:
//   D_i  = sum c_i * (relu(g+c_i)      + relu(g))
//   D_j0 = sum c_j * (relu(g+c_j)      + relu(g))          [i rejected]
//   D_j1 = sum c_j * (relu(g+c_i+c_j)  + relu(g+c_i))      [i accepted]
// Each warp leader writes its int4 partial into BOTH CTAs' s_wpart
// (local slot w, peer slot 8+w via mapa/st.shared::cluster), arrives on both
// mbars (count=16). All threads try_wait(acquire.cluster), then both CTAs
// reduce the identical 16 partials -> bit-identical exact-int32 decisions.
// ---------------------------------------------------------------------------
__global__ __launch_bounds__(NTHR, 1) __cluster_dims__(2, 1, 1)
void k_main(const float* __restrict__ state, const int* __restrict__ perm,
            float* __restrict__ out) {
    __shared__ float s_state[N_BITS];
    __shared__ int   s_perm2[N_BITS + 4];   // perm * COLBYTES, padded
    __shared__ int4  s_wpart[2][32];
    __shared__ uint64_t s_mbar;

    int t = threadIdx.x;
    uint32_t rank;
    asm("mov.u32 %0, %%cluster_ctarank;" : "=r"(rank));
    uint32_t peer = rank ^ 1u;

    for (int k = t; k < N_BITS; k += NTHR) {
        s_perm2[k] = perm[k] << 14;          // * COLBYTES
        s_state[k] = state[k];
    }
    if (t < 4)  s_perm2[N_BITS + t] = 0;     // sentinel (prefetch-only)
    if (t < 64) reinterpret_cast<int4*>(s_wpart)[t] = make_int4(0, 0, 0, 0);

    uint32_t mb    = smem_u32(&s_mbar);
    uint32_t wbase = smem_u32(&s_wpart[0][0]);
    if (t == 0) MBAR_INIT(mb, 16);           // 8 local + 8 remote leaders

    // this CTA's 4096-row half: rows rank*4096 + t*16 .. +15
    const char* __restrict__ Cb =
        reinterpret_cast<const char*>(g_C) + rank * (N_PAT) + t * 32;  // rank*4096 rows*2B

    int g2[8], m2[8];
    #pragma unroll
    for (int k = 0; k < 8; k++) {
        int a = g_g0[rank * 4096 + t * 16 + 2 * k];
        int b = g_g0[rank * 4096 + t * 16 + 2 * k + 1];
        g2[k] = (a & 0xFFFF) | (b << 16);
        m2[k] = (max(a, 0) & 0xFFFF) | (max(b, 0) << 16);
    }
    __syncthreads();
    CLUSTER_SYNC();   // peer's mbar init + s_wpart zeroing visible before any remote store

    // column buffers: [parity][2 x uint4] for bit-i and bit-j of a group
    uint4 bI[2][2], bJ[2][2];
    {
        const uint4* ci = reinterpret_cast<const uint4*>(Cb + s_perm2[0]);
        const uint4* cj = reinterpret_cast<const uint4*>(Cb + s_perm2[1]);
        #pragma unroll
        for (int q = 0; q < 2; q++) { bI[0][q] = __ldg(ci + q); bJ[0][q] = __ldg(cj + q); }
    }

    #pragma unroll 2
    for (int s = 0; s < N_BITS / 2; s++) {
        int p = s & 1;
        // prefetch next group's two columns (sentinel-padded, no clamp)
        {
            const uint4* ci = reinterpret_cast<const uint4*>(Cb + s_perm2[2 * s + 2]);
            const uint4* cj = reinterpret_cast<const uint4*>(Cb + s_perm2[2 * s + 3]);
            #pragma unroll
            for (int q = 0; q < 2; q++) { bI[p ^ 1][q] = __ldg(ci + q); bJ[p ^ 1][q] = __ldg(cj + q); }
        }

        int Di1 = 0, Di2 = 0, Dj01 = 0, Dj02 = 0, Dj11 = 0, Dj12 = 0;

#define W2(k, ci0, ci1, cj0, cj1) {                                      \
        int gi0 = __vadd2(g2[k],     (int)(ci0));                        \
        int gi1 = __vadd2(g2[k + 1], (int)(ci1));                        \
        int gj0 = __vadd2(g2[k],     (int)(cj0));                        \
        int gj1 = __vadd2(g2[k + 1], (int)(cj1));                        \
        int gx0 = __vadd2(gi0,       (int)(cj0));                        \
        int gx1 = __vadd2(gi1,       (int)(cj1));                        \
        int mi0 = (int)__vmaxs2((unsigned)gi0, 0u);                      \
        int mi1 = (int)__vmaxs2((unsigned)gi1, 0u);                      \
        int mj0 = (int)__vmaxs2((unsigned)gj0, 0u);                      \
        int mj1 = (int)__vmaxs2((unsigned)gj1, 0u);                      \
        int mx0 = (int)__vmaxs2((unsigned)gx0, 0u);                      \
        int mx1 = (int)__vmaxs2((unsigned)gx1, 0u);                      \
        int c4i = __byte_perm((int)(ci0), (int)(ci1), 0x6420);           \
        int c4j = __byte_perm((int)(cj0), (int)(cj1), 0x6420);           \
        Di1  = __dp2a_lo(mi0,       c4i, Di1);                           \
        Di1  = __dp2a_hi(mi1,       c4i, Di1);                           \
        Di2  = __dp2a_lo(m2[k],     c4i, Di2);                           \
        Di2  = __dp2a_hi(m2[k + 1], c4i, Di2);                           \
        Dj01 = __dp2a_lo(mj0,       c4j, Dj01);                          \
        Dj01 = __dp2a_hi(mj1,       c4j, Dj01);                          \
        Dj02 = __dp2a_lo(m2[k],     c4j, Dj02);                          \
        Dj02 = __dp2a_hi(m2[k + 1], c4j, Dj02);                          \
        Dj11 = __dp2a_lo(mx0,       c4j, Dj11);                          \
        Dj11 = __dp2a_hi(mx1,       c4j, Dj11);                          \
        Dj12 = __dp2a_lo(mi0,       c4j, Dj12);                          \
        Dj12 = __dp2a_hi(mi1,       c4j, Dj12); }

        W2(0, bI[p][0].x, bI[p][0].y, bJ[p][0].x, bJ[p][0].y)
        W2(2, bI[p][0].z, bI[p][0].w, bJ[p][0].z, bJ[p][0].w)
        W2(4, bI[p][1].x, bI[p][1].y, bJ[p][1].x, bJ[p][1].y)
        W2(6, bI[p][1].z, bI[p][1].w, bJ[p][1].z, bJ[p][1].w)
#undef W2

        int wDi  = __reduce_add_sync(0xffffffffu, Di1 + Di2);
        int wDj0 = __reduce_add_sync(0xffffffffu, Dj01 + Dj02);
        int wDj1 = __reduce_add_sync(0xffffffffu, Dj11 + Dj12);
        if ((t & 31) == 0) {
            int w = t >> 5;
            s_wpart[p][w] = make_int4(wDi, wDj0, wDj1, 0);              // local slot w
            uint32_t peerSlot = wbase + (uint32_t)(p * 32 + 8 + w) * 16; // my slot 8+w on peer
            uint64_t d0 = (uint64_t)(uint32_t)wDi  | ((uint64_t)(uint32_t)wDj0 << 32);
            uint64_t d1 = (uint64_t)(uint32_t)wDj1;
            ST_PEER_B64(peerSlot,     peer, d0);
            ST_PEER_B64(peerSlot + 8, peer, d1);
            MBAR_ARRIVE_LOCAL(mb);
            MBAR_ARRIVE_PEER(mb, peer);
        }

        MBAR_WAIT_CL(mb, s & 1);

        int4 v = s_wpart[p][t & 31];                 // 16 live slots, 16..31 zero
        int Ti  = __reduce_add_sync(0xffffffffu, v.x);
        int Tj0 = __reduce_add_sync(0xffffffffu, v.y);
        int Tj1 = __reduce_add_sync(0xffffffffu, v.z);

        bool ai = Ti > 0;
        bool aj = (ai ? Tj1 : Tj0) > 0;

        if (ai | aj) {    // single region: masked adds, then recompute m
            int mi = -(int)ai;    // 0 or 0xFFFFFFFF (AND-mask on packed s16)
            int mj = -(int)aj;
            #pragma unroll
            for (int q = 0; q < 2; q++) {
                g2[4*q+0] = __vadd2(__vadd2(g2[4*q+0], (int)bI[p][q].x & mi), (int)bJ[p][q].x & mj);
                g2[4*q+1] = __vadd2(__vadd2(g2[4*q+1], (int)bI[p][q].y & mi), (int)bJ[p][q].y & mj);
                g2[4*q+2] = __vadd2(__vadd2(g2[4*q+2], (int)bI[p][q].z & mi), (int)bJ[p][q].z & mj);
                g2[4*q+3] = __vadd2(__vadd2(g2[4*q+3], (int)bI[p][q].w & mi), (int)bJ[p][q].w & mj);
            }
            #pragma unroll
            for (int k = 0; k < 8; k++) m2[k] = (int)__vmaxs2((unsigned)g2[k], 0u);
            if (rank == 0 && t == 0) {
                if (ai) { int ip = s_perm2[2 * s]     >> 14; out[ip] = -s_state[ip]; }
                if (aj) { int ip = s_perm2[2 * s + 1] >> 14; out[ip] = -s_state[ip]; }
            }
        }
    }

    CLUSTER_SYNC();   // quiesce cross-CTA traffic before exit
}

// ---------------------------------------------------------------------------
extern "C" void kernel_launch(void* const* d_in, const int* in_sizes, int n_in,
                              void* d_out, int out_size) {
    const float* W     = (const float*)d_in[0];
    const float* state = (const float*)d_in[1];
    const int*   perm  = (const int*)d_in[2];
    float*       out   = (float*)d_out;

    dim3 b1(32, 8), g1(N_BITS / 32, N_PAT / 128);
    k_buildU<<<g1, b1>>>(W, state);
    k_h0t<<<N_BITS / 256, 256>>>(state, out);
    k_main<<<2, NTHR>>>(state, perm, out);   // __cluster_dims__(2,1,1) applies
}

// round 15
// speedup vs baseline: 1.3458x; 1.3458x over previous
#include <cuda_runtime.h>
#include <cstdint>

#define N_PAT 8192
#define N_BITS 4096
#define NTHR 512          // 16 warps; 16 rows per thread
#define COLBYTES (N_PAT * 2)   // 16384 = 1 << 14

// c'[i][r] = -state[i]*W[r][i] in {+1,-1}.
// g_C  : s16 copy (vadd2 operands).  g_C8 : s8 copy (dp2a operands).
// Halved domain: g = h/2; flip i => g_new = g + c'[i].
__device__ short         g_C [(size_t)N_BITS * N_PAT];  // 64 MB
__device__ unsigned char g_C8[(size_t)N_BITS * N_PAT];  // 32 MB
__device__ int           g_g0[N_PAT];

// ---------------------------------------------------------------------------
__global__ void k_buildU(const float* __restrict__ W, const float* __restrict__ state) {
    __shared__ unsigned char sm[32][132];
    int i0 = blockIdx.x * 32;
    int r0 = blockIdx.y * 128;
    int tx = threadIdx.x, ty = threadIdx.y;
    float v = state[i0 + tx];
    #pragma unroll
    for (int j = 0; j < 16; j++) {
        float w = W[(size_t)(r0 + ty + j * 8) * N_BITS + i0 + tx];
        sm[tx][ty + j * 8] = (w == v) ? 1 : 0;
    }
    __syncthreads();
    #pragma unroll
    for (int jj = 0; jj < 4; jj++) {
        int il = ty + jj * 8;
        int c0 = 1 - 2 * (int)sm[il][4 * tx + 0];
        int c1 = 1 - 2 * (int)sm[il][4 * tx + 1];
        int c2 = 1 - 2 * (int)sm[il][4 * tx + 2];
        int c3 = 1 - 2 * (int)sm[il][4 * tx + 3];
        short4 v16 = make_short4((short)c0, (short)c1, (short)c2, (short)c3);
        uchar4 v8  = make_uchar4((unsigned char)c0, (unsigned char)c1,
                                 (unsigned char)c2, (unsigned char)c3);
        size_t base = (size_t)(i0 + il) * N_PAT + r0 + 4 * tx;
        *reinterpret_cast<short4*>(&g_C[base])  = v16;
        *reinterpret_cast<uchar4*>(&g_C8[base]) = v8;
    }
}

// ---------------------------------------------------------------------------
__global__ void k_h0t(const float* __restrict__ state, float* __restrict__ out) {
    int t = blockIdx.x * blockDim.x + threadIdx.x;   // 0..4095 (row pair)
    out[t] = state[t];
    const int* col = reinterpret_cast<const int*>(g_C) + t;
    int acc2 = 0;
    #pragma unroll 8
    for (int i = 0; i < N_BITS; i++)
        acc2 = __vadd2(acc2, col[(size_t)i * (N_PAT / 2)]);
    int lo = (int)(short)(acc2 & 0xFFFF);
    int hi = acc2 >> 16;
    g_g0[2 * t]     = -(lo >> 1);
    g_g0[2 * t + 1] = -(hi >> 1);
}

// ---------------------------------------------------------------------------
// Main: single CTA, 512 threads (16 warps), 16 rows/thread as 8 s16x2 regs
// (g) + m = relu(g). TWO bits per barrier: exact deltas
//   D_i  = sum c_i * (relu(g+c_i)      + relu(g))
//   D_j0 = sum c_j * (relu(g+c_j)      + relu(g))          [i rejected]
//   D_j1 = sum c_j * (relu(g+c_i+c_j)  + relu(g+c_i))      [i accepted]
// One STS.128/warp, ONE __syncthreads, LDS.128 + 3x REDUX, decide both bits.
// dp2a s8 operands load directly from g_C8 (no PRMT in the body).
// s_perm2 holds perm*COLBYTES (byte offsets, sentinel-padded); s8 offsets
// derived as >>1. Index recovered as offset >> 14 in the rare accept path.
// ---------------------------------------------------------------------------
__global__ __launch_bounds__(NTHR, 1)
void k_main(const float* __restrict__ state, const int* __restrict__ perm,
            float* __restrict__ out) {
    __shared__ float s_state[N_BITS];
    __shared__ int   s_perm2[N_BITS + 4];   // perm * COLBYTES, padded
    __shared__ int4  s_wpart[2][32];

    int t = threadIdx.x;
    for (int k = t; k < N_BITS; k += NTHR) {
        s_perm2[k] = perm[k] << 14;          // * COLBYTES
        s_state[k] = state[k];
    }
    if (t < 4)  s_perm2[N_BITS + t] = 0;     // sentinel columns (prefetch-only)
    if (t < 64) reinterpret_cast<int4*>(s_wpart)[t] = make_int4(0, 0, 0, 0);

    const char* __restrict__ Cb  = reinterpret_cast<const char*>(g_C)  + t * 32;  // 16 rows, s16
    const char* __restrict__ Cb8 = reinterpret_cast<const char*>(g_C8) + t * 16;  // 16 rows, s8

    int g2[8], m2[8];
    #pragma unroll
    for (int k = 0; k < 8; k++) {
        int a = g_g0[t * 16 + 2 * k];
        int b = g_g0[t * 16 + 2 * k + 1];
        g2[k] = (a & 0xFFFF) | (b << 16);
        m2[k] = (max(a, 0) & 0xFFFF) | (max(b, 0) << 16);
    }
    __syncthreads();

    // column buffers: [parity]; s16 pairs (2 x uint4) + s8 (1 x uint4) per bit
    uint4 bI[2][2], bJ[2][2], b8I[2], b8J[2];
    {
        int oi = s_perm2[0], oj = s_perm2[1];
        const uint4* ci = reinterpret_cast<const uint4*>(Cb + oi);
        const uint4* cj = reinterpret_cast<const uint4*>(Cb + oj);
        #pragma unroll
        for (int q = 0; q < 2; q++) { bI[0][q] = __ldg(ci + q); bJ[0][q] = __ldg(cj + q); }
        b8I[0] = __ldg(reinterpret_cast<const uint4*>(Cb8 + (oi >> 1)));
        b8J[0] = __ldg(reinterpret_cast<const uint4*>(Cb8 + (oj >> 1)));
    }

    #pragma unroll 2
    for (int s = 0; s < N_BITS / 2; s++) {
        int p = s & 1;
        // prefetch next group's two columns (sentinel-padded, no clamp)
        {
            int oi = s_perm2[2 * s + 2], oj = s_perm2[2 * s + 3];
            const uint4* ci = reinterpret_cast<const uint4*>(Cb + oi);
            const uint4* cj = reinterpret_cast<const uint4*>(Cb + oj);
            #pragma unroll
            for (int q = 0; q < 2; q++) { bI[p ^ 1][q] = __ldg(ci + q); bJ[p ^ 1][q] = __ldg(cj + q); }
            b8I[p ^ 1] = __ldg(reinterpret_cast<const uint4*>(Cb8 + (oi >> 1)));
            b8J[p ^ 1] = __ldg(reinterpret_cast<const uint4*>(Cb8 + (oj >> 1)));
        }

        int Di1 = 0, Di2 = 0, Dj01 = 0, Dj02 = 0, Dj11 = 0, Dj12 = 0;

#define W2(k, ci0, ci1, cj0, cj1, c4i, c4j) {                            \
        int gi0 = __vadd2(g2[k],     (int)(ci0));                        \
        int gi1 = __vadd2(g2[k + 1], (int)(ci1));                        \
        int gj0 = __vadd2(g2[k],     (int)(cj0));                        \
        int gj1 = __vadd2(g2[k + 1], (int)(cj1));                        \
        int gx0 = __vadd2(gi0,       (int)(cj0));                        \
        int gx1 = __vadd2(gi1,       (int)(cj1));                        \
        int mi0 = (int)__vmaxs2((unsigned)gi0, 0u);                      \
        int mi1 = (int)__vmaxs2((unsigned)gi1, 0u);                      \
        int mj0 = (int)__vmaxs2((unsigned)gj0, 0u);                      \
        int mj1 = (int)__vmaxs2((unsigned)gj1, 0u);                      \
        int mx0 = (int)__vmaxs2((unsigned)gx0, 0u);                      \
        int mx1 = (int)__vmaxs2((unsigned)gx1, 0u);                      \
        Di1  = __dp2a_lo(mi0,       (int)(c4i), Di1);                    \
        Di1  = __dp2a_hi(mi1,       (int)(c4i), Di1);                    \
        Di2  = __dp2a_lo(m2[k],     (int)(c4i), Di2);                    \
        Di2  = __dp2a_hi(m2[k + 1], (int)(c4i), Di2);                    \
        Dj01 = __dp2a_lo(mj0,       (int)(c4j), Dj01);                   \
        Dj01 = __dp2a_hi(mj1,       (int)(c4j), Dj01);                   \
        Dj02 = __dp2a_lo(m2[k],     (int)(c4j), Dj02);                   \
        Dj02 = __dp2a_hi(m2[k + 1], (int)(c4j), Dj02);                   \
        Dj11 = __dp2a_lo(mx0,       (int)(c4j), Dj11);                   \
        Dj11 = __dp2a_hi(mx1,       (int)(c4j), Dj11);                   \
        Dj12 = __dp2a_lo(mi0,       (int)(c4j), Dj12);                   \
        Dj12 = __dp2a_hi(mi1,       (int)(c4j), Dj12); }

        W2(0, bI[p][0].x, bI[p][0].y, bJ[p][0].x, bJ[p][0].y, b8I[p].x, b8J[p].x)
        W2(2, bI[p][0].z, bI[p][0].w, bJ[p][0].z, bJ[p][0].w, b8I[p].y, b8J[p].y)
        W2(4, bI[p][1].x, bI[p][1].y, bJ[p][1].x, bJ[p][1].y, b8I[p].z, b8J[p].z)
        W2(6, bI[p][1].z, bI[p][1].w, bJ[p][1].z, bJ[p][1].w, b8I[p].w, b8J[p].w)
#undef W2

        int wDi  = __reduce_add_sync(0xffffffffu, Di1 + Di2);
        int wDj0 = __reduce_add_sync(0xffffffffu, Dj01 + Dj02);
        int wDj1 = __reduce_add_sync(0xffffffffu, Dj11 + Dj12);
        if ((t & 31) == 0) s_wpart[p][t >> 5] = make_int4(wDi, wDj0, wDj1, 0);

        __syncthreads();

        int4 v = s_wpart[p][t & 31];                 // slots 16..31 stay zero
        int Ti  = __reduce_add_sync(0xffffffffu, v.x);
        int Tj0 = __reduce_add_sync(0xffffffffu, v.y);
        int Tj1 = __reduce_add_sync(0xffffffffu, v.z);

        bool ai = Ti > 0;
        bool aj = (ai ? Tj1 : Tj0) > 0;

        if (ai | aj) {    // single region: masked adds, then recompute m
            int mi = -(int)ai;    // 0 or 0xFFFFFFFF (AND-mask on packed s16)
            int mj = -(int)aj;
            #pragma unroll
            for (int q = 0; q < 2; q++) {
                g2[4*q+0] = __vadd2(__vadd2(g2[4*q+0], (int)bI[p][q].x & mi), (int)bJ[p][q].x & mj);
                g2[4*q+1] = __vadd2(__vadd2(g2[4*q+1], (int)bI[p][q].y & mi), (int)bJ[p][q].y & mj);
                g2[4*q+2] = __vadd2(__vadd2(g2[4*q+2], (int)bI[p][q].z & mi), (int)bJ[p][q].z & mj);
                g2[4*q+3] = __vadd2(__vadd2(g2[4*q+3], (int)bI[p][q].w & mi), (int)bJ[p][q].w & mj);
            }
            #pragma unroll
            for (int k = 0; k < 8; k++) m2[k] = (int)__vmaxs2((unsigned)g2[k], 0u);
            if (t == 0) {
                if (ai) { int ip = s_perm2[2 * s]     >> 14; out[ip] = -s_state[ip]; }
                if (aj) { int ip = s_perm2[2 * s + 1] >> 14; out[ip] = -s_state[ip]; }
            }
        }
    }
}

// ---------------------------------------------------------------------------
extern "C" void kernel_launch(void* const* d_in, const int* in_sizes, int n_in,
                              void* d_out, int out_size) {
    const float* W     = (const float*)d_in[0];
    const float* state = (const float*)d_in[1];
    const int*   perm  = (const int*)d_in[2];
    float*       out   = (float*)d_out;

    dim3 b1(32, 8), g1(N_BITS / 32, N_PAT / 128);
    k_buildU<<<g1, b1>>>(W, state);
    k_h0t<<<N_BITS / 256, 256>>>(state, out);
    k_main<<<1, NTHR>>>(state, perm, out);
}

// round 16
// speedup vs baseline: 1.4315x; 1.0637x over previous
#include <cuda_runtime.h>
#include <cstdint>

#define N_PAT 8192
#define N_BITS 4096
#define NTHR 512          // 16 warps; 16 rows per thread

// c'[i][r] = -state[i]*W[r][i] in {+1,-1}, stored s16.
// Halved domain: g = h/2; flip i => g_new = g + c'[i].
__device__ short g_C[(size_t)N_BITS * N_PAT];  // 64 MB scratch
__device__ int   g_g0[N_PAT];

// ---------------------------------------------------------------------------
__global__ void k_buildU(const float* __restrict__ W, const float* __restrict__ state) {
    __shared__ unsigned char sm[32][132];
    int i0 = blockIdx.x * 32;
    int r0 = blockIdx.y * 128;
    int tx = threadIdx.x, ty = threadIdx.y;
    float v = state[i0 + tx];
    #pragma unroll
    for (int j = 0; j < 16; j++) {
        float w = W[(size_t)(r0 + ty + j * 8) * N_BITS + i0 + tx];
        sm[tx][ty + j * 8] = (w == v) ? 1 : 0;
    }
    __syncthreads();
    #pragma unroll
    for (int jj = 0; jj < 4; jj++) {
        int il = ty + jj * 8;
        short4 val;
        val.x = (short)(1 - 2 * (int)sm[il][4 * tx + 0]);
        val.y = (short)(1 - 2 * (int)sm[il][4 * tx + 1]);
        val.z = (short)(1 - 2 * (int)sm[il][4 * tx + 2]);
        val.w = (short)(1 - 2 * (int)sm[il][4 * tx + 3]);
        *reinterpret_cast<short4*>(&g_C[(size_t)(i0 + il) * N_PAT + r0 + 4 * tx]) = val;
    }
}

// ---------------------------------------------------------------------------
__global__ void k_h0t(const float* __restrict__ state, float* __restrict__ out) {
    int t = blockIdx.x * blockDim.x + threadIdx.x;   // 0..4095 (row pair)
    out[t] = state[t];
    const int* col = reinterpret_cast<const int*>(g_C) + t;
    int acc2 = 0;
    #pragma unroll 8
    for (int i = 0; i < N_BITS; i++)
        acc2 = __vadd2(acc2, col[(size_t)i * (N_PAT / 2)]);
    int lo = (int)(short)(acc2 & 0xFFFF);
    int hi = acc2 >> 16;
    g_g0[2 * t]     = -(lo >> 1);
    g_g0[2 * t + 1] = -(hi >> 1);
}

// ---------------------------------------------------------------------------
// Main: single CTA, 512 threads (16 warps), 16 rows/thread as 8 s16x2 regs
// (g) + m = relu(g). TWO bits per barrier: exact deltas
//   D_i  = sum c_i * (relu(g+c_i)      + relu(g))
//   D_j0 = sum c_j * (relu(g+c_j)      + relu(g))          [i rejected]
//   D_j1 = sum c_j * (relu(g+c_i+c_j)  + relu(g+c_i))      [i accepted]
// One STS.128/warp, ONE __syncthreads, LDS.128 + 3x REDUX, decide both bits.
// Accept path: single if(ai|aj) region with sign-mask ANDs (1 BSSY, not 3).
// Columns double-buffered in registers via LDG one group ahead.
// ---------------------------------------------------------------------------
__global__ __launch_bounds__(NTHR, 1)
void k_main(const float* __restrict__ state, const int* __restrict__ perm,
            float* __restrict__ out) {
    __shared__ float s_state[N_BITS];
    __shared__ int   s_perm[N_BITS];
    __shared__ int4  s_wpart[2][32];

    int t = threadIdx.x;
    for (int k = t; k < N_BITS; k += NTHR) {
        s_perm[k]  = perm[k];
        s_state[k] = state[k];
    }
    if (t < 64) reinterpret_cast<int4*>(s_wpart)[t] = make_int4(0, 0, 0, 0);

    const short* __restrict__ Cb = g_C + t * 16;   // this thread's 16-row slice

    int g2[8], m2[8];
    #pragma unroll
    for (int k = 0; k < 8; k++) {
        int a = g_g0[t * 16 + 2 * k];
        int b = g_g0[t * 16 + 2 * k + 1];
        g2[k] = (a & 0xFFFF) | (b << 16);
        m2[k] = (max(a, 0) & 0xFFFF) | (max(b, 0) << 16);
    }
    __syncthreads();

    // column buffers: [parity][2 x uint4] for bit-i and bit-j of a group
    uint4 bI[2][2], bJ[2][2];
    {
        const uint4* ci = reinterpret_cast<const uint4*>(Cb + (size_t)s_perm[0] * N_PAT);
        const uint4* cj = reinterpret_cast<const uint4*>(Cb + (size_t)s_perm[1] * N_PAT);
        #pragma unroll
        for (int q = 0; q < 2; q++) { bI[0][q] = __ldg(ci + q); bJ[0][q] = __ldg(cj + q); }
    }

    #pragma unroll 2
    for (int s = 0; s < N_BITS / 2; s++) {
        int p = s & 1;
        // prefetch next group's two columns (clamped)
        {
            int i2 = min(2 * s + 2, N_BITS - 2);
            int j2 = min(2 * s + 3, N_BITS - 1);
            const uint4* ci = reinterpret_cast<const uint4*>(Cb + (size_t)s_perm[i2] * N_PAT);
            const uint4* cj = reinterpret_cast<const uint4*>(Cb + (size_t)s_perm[j2] * N_PAT);
            #pragma unroll
            for (int q = 0; q < 2; q++) { bI[p ^ 1][q] = __ldg(ci + q); bJ[p ^ 1][q] = __ldg(cj + q); }
        }

        int Di1 = 0, Di2 = 0, Dj01 = 0, Dj02 = 0, Dj11 = 0, Dj12 = 0;

#define W2(k, ci0, ci1, cj0, cj1) {                                      \
        int gi0 = __vadd2(g2[k],     (int)(ci0));                        \
        int gi1 = __vadd2(g2[k + 1], (int)(ci1));                        \
        int gj0 = __vadd2(g2[k],     (int)(cj0));                        \
        int gj1 = __vadd2(g2[k + 1], (int)(cj1));                        \
        int gx0 = __vadd2(gi0,       (int)(cj0));                        \
        int gx1 = __vadd2(gi1,       (int)(cj1));                        \
        int mi0 = (int)__vmaxs2((unsigned)gi0, 0u);                      \
        int mi1 = (int)__vmaxs2((unsigned)gi1, 0u);                      \
        int mj0 = (int)__vmaxs2((unsigned)gj0, 0u);                      \
        int mj1 = (int)__vmaxs2((unsigned)gj1, 0u);                      \
        int mx0 = (int)__vmaxs2((unsigned)gx0, 0u);                      \
        int mx1 = (int)__vmaxs2((unsigned)gx1, 0u);                      \
        int c4i = __byte_perm((int)(ci0), (int)(ci1), 0x6420);           \
        int c4j = __byte_perm((int)(cj0), (int)(cj1), 0x6420);           \
        Di1  = __dp2a_lo(mi0,       c4i, Di1);                           \
        Di1  = __dp2a_hi(mi1,       c4i, Di1);                           \
        Di2  = __dp2a_lo(m2[k],     c4i, Di2);                           \
        Di2  = __dp2a_hi(m2[k + 1], c4i, Di2);                           \
        Dj01 = __dp2a_lo(mj0,       c4j, Dj01);                          \
        Dj01 = __dp2a_hi(mj1,       c4j, Dj01);                          \
        Dj02 = __dp2a_lo(m2[k],     c4j, Dj02);                          \
        Dj02 = __dp2a_hi(m2[k + 1], c4j, Dj02);                          \
        Dj11 = __dp2a_lo(mx0,       c4j, Dj11);                          \
        Dj11 = __dp2a_hi(mx1,       c4j, Dj11);                          \
        Dj12 = __dp2a_lo(mi0,       c4j, Dj12);                          \
        Dj12 = __dp2a_hi(mi1,       c4j, Dj12); }

        W2(0, bI[p][0].x, bI[p][0].y, bJ[p][0].x, bJ[p][0].y)
        W2(2, bI[p][0].z, bI[p][0].w, bJ[p][0].z, bJ[p][0].w)
        W2(4, bI[p][1].x, bI[p][1].y, bJ[p][1].x, bJ[p][1].y)
        W2(6, bI[p][1].z, bI[p][1].w, bJ[p][1].z, bJ[p][1].w)
#undef W2

        int wDi  = __reduce_add_sync(0xffffffffu, Di1 + Di2);
        int wDj0 = __reduce_add_sync(0xffffffffu, Dj01 + Dj02);
        int wDj1 = __reduce_add_sync(0xffffffffu, Dj11 + Dj12);
        if ((t & 31) == 0) s_wpart[p][t >> 5] = make_int4(wDi, wDj0, wDj1, 0);

        __syncthreads();

        int4 v = s_wpart[p][t & 31];                 // slots 16..31 stay zero
        int Ti  = __reduce_add_sync(0xffffffffu, v.x);
        int Tj0 = __reduce_add_sync(0xffffffffu, v.y);
        int Tj1 = __reduce_add_sync(0xffffffffu, v.z);

        bool ai = Ti > 0;
        bool aj = (ai ? Tj1 : Tj0) > 0;

        if (ai | aj) {    // single region: masked adds, then recompute m
            int mi = -(int)ai;    // 0 or 0xFFFFFFFF (AND-mask on packed s16)
            int mj = -(int)aj;
            #pragma unroll
            for (int q = 0; q < 2; q++) {
                g2[4*q+0] = __vadd2(__vadd2(g2[4*q+0], (int)bI[p][q].x & mi), (int)bJ[p][q].x & mj);
                g2[4*q+1] = __vadd2(__vadd2(g2[4*q+1], (int)bI[p][q].y & mi), (int)bJ[p][q].y & mj);
                g2[4*q+2] = __vadd2(__vadd2(g2[4*q+2], (int)bI[p][q].z & mi), (int)bJ[p][q].z & mj);
                g2[4*q+3] = __vadd2(__vadd2(g2[4*q+3], (int)bI[p][q].w & mi), (int)bJ[p][q].w & mj);
            }
            #pragma unroll
            for (int k = 0; k < 8; k++) m2[k] = (int)__vmaxs2((unsigned)g2[k], 0u);
            if (t == 0) {
                if (ai) { int ip = s_perm[2 * s];     out[ip] = -s_state[ip]; }
                if (aj) { int ip = s_perm[2 * s + 1]; out[ip] = -s_state[ip]; }
            }
        }
    }
}

// ---------------------------------------------------------------------------
extern "C" void kernel_launch(void* const* d_in, const int* in_sizes, int n_in,
                              void* d_out, int out_size) {
    const float* W     = (const float*)d_in[0];
    const float* state = (const float*)d_in[1];
    const int*   perm  = (const int*)d_in[2];
    float*       out   = (float*)d_out;

    dim3 b1(32, 8), g1(N_BITS / 32, N_PAT / 128);
    k_buildU<<<g1, b1>>>(W, state);
    k_h0t<<<N_BITS / 256, 256>>>(state, out);
    k_main<<<1, NTHR>>>(state, perm, out);
}